// round 3
// baseline (speedup 1.0000x reference)
#include <cuda_runtime.h>

typedef unsigned long long u64;

#define TRP 257           // padded stride for col-major x tile
#define TR  256           // rows per CTA
#define NTHREADS 256

// float offsets inside weight buffer
#define OW1T 0
#define OW1S 1024
#define OW2T 2048
#define OW2S 2304
#define OW3T 2560
#define OW3S 2816
#define OW4T 3072
#define OW4S 3328
#define OW5T 3584
#define OW5S 4608
#define OB1T 5632
#define OB1S 5648
#define OB2T 5664
#define OB2S 5680
#define OB3T 5696
#define OB3S 5712
#define OB4T 5728
#define OB4S 5744
#define OB5T 5760
#define OB5S 5824
#define WTOT 5888

#define XS_FLOATS (128 * TRP)
#define SMEM_FLOATS (XS_FLOATS + WTOT)
#define SMEM_BYTES (SMEM_FLOATS * 4)

__device__ __forceinline__ u64 pack2(float a, float b) {
    u64 r; asm("mov.b64 %0, {%1, %2};" : "=l"(r) : "f"(a), "f"(b)); return r;
}
__device__ __forceinline__ void unpack2(u64 v, float& a, float& b) {
    asm("mov.b64 {%0, %1}, %2;" : "=f"(a), "=f"(b) : "l"(v));
}
__device__ __forceinline__ u64 ffma2(u64 a, u64 b, u64 c) {
    u64 d; asm("fma.rn.f32x2 %0, %1, %2, %3;" : "=l"(d) : "l"(a), "l"(b), "l"(c)); return d;
}

// tanh(z) = 1 - 2/(e^{2z}+1); saturates correctly at +/-inf.
__device__ __forceinline__ float tanh_fast(float z) {
    float e = __expf(2.0f * z);
    return 1.0f - __fdividef(2.0f, e + 1.0f);
}

// h[16] = relu(h @ W[16x16] + b); W,b broadcast from shared
__device__ __forceinline__ void dense16_relu(float* h, const float* w, const float* b) {
    u64 acc[8];
    const u64* bp = (const u64*)b;
#pragma unroll
    for (int i = 0; i < 8; i++) acc[i] = bp[i];
#pragma unroll
    for (int k = 0; k < 16; k++) {
        u64 xx = pack2(h[k], h[k]);
        const ulonglong2* wp = (const ulonglong2*)(w + k * 16);
#pragma unroll
        for (int i = 0; i < 4; i++) {
            ulonglong2 wv = wp[i];
            acc[2 * i]     = ffma2(xx, wv.x, acc[2 * i]);
            acc[2 * i + 1] = ffma2(xx, wv.y, acc[2 * i + 1]);
        }
    }
#pragma unroll
    for (int i = 0; i < 8; i++) {
        float a, bv; unpack2(acc[i], a, bv);
        h[2 * i]     = fmaxf(a, 0.f);
        h[2 * i + 1] = fmaxf(bv, 0.f);
    }
}

__global__ void __launch_bounds__(NTHREADS, 1)
realnvp_kernel(const float* __restrict__ x, const float* __restrict__ masks,
               const float* __restrict__ tW1, const float* __restrict__ tb1,
               const float* __restrict__ tW2, const float* __restrict__ tb2,
               const float* __restrict__ tW3, const float* __restrict__ tb3,
               const float* __restrict__ tW4, const float* __restrict__ tb4,
               const float* __restrict__ tW5, const float* __restrict__ tb5,
               const float* __restrict__ sW1, const float* __restrict__ sb1,
               const float* __restrict__ sW2, const float* __restrict__ sb2,
               const float* __restrict__ sW3, const float* __restrict__ sb3,
               const float* __restrict__ sW4, const float* __restrict__ sb4,
               const float* __restrict__ sW5, const float* __restrict__ sb5,
               float* __restrict__ out, int rows) {
    extern __shared__ float sm[];
    float* xs   = sm;              // [128 cols][TRP] col-major x tile
    float* wbuf = sm + XS_FLOATS;  // per-layer staged weights

    const int tid = threadIdx.x;
    const int row0 = blockIdx.x * TR;
    const int r = tid;
    const bool active = (row0 + r) < rows;

    // ---- stage x tile (coalesced float4 loads, transposed scatter) ----
    {
        const float4* xg = (const float4*)(x + (size_t)row0 * 128);
        for (int idx = tid; idx < TR * 32; idx += NTHREADS) {
            int rr = idx >> 5, c4 = idx & 31;
            if (row0 + rr < rows) {
                float4 v = xg[idx];
                int cb = c4 * 4;
                xs[(cb + 0) * TRP + rr] = v.x;
                xs[(cb + 1) * TRP + rr] = v.y;
                xs[(cb + 2) * TRP + rr] = v.z;
                xs[(cb + 3) * TRP + rr] = v.w;
            }
        }
    }

    float ld = 0.f;

    for (int li = 0; li < 6; ++li) {
        const int l = 5 - li;  // reversed layer order (training path)
        __syncthreads();       // wbuf free (and x tile staged on first iter)

        // mask[l][0]==1 -> input half cols [0,64), update half [64,128)
        const int inoff = (masks[l * 128] > 0.5f) ? 0 : 64;
        const int upoff = 64 - inoff;

        // ---- stage weights: active 64 rows of W1, active 64 cols of W5 ----
        for (int i = tid; i < 1024; i += NTHREADS) {
            wbuf[OW1T + i] = tW1[l * 2048 + inoff * 16 + i];
            wbuf[OW1S + i] = sW1[l * 2048 + inoff * 16 + i];
            int k = i >> 6, j = i & 63;
            wbuf[OW5T + i] = tW5[l * 2048 + k * 128 + upoff + j];
            wbuf[OW5S + i] = sW5[l * 2048 + k * 128 + upoff + j];
        }
        {
            int i = tid;  // 256 threads cover each 16x16 in one shot
            wbuf[OW2T + i] = tW2[l * 256 + i]; wbuf[OW2S + i] = sW2[l * 256 + i];
            wbuf[OW3T + i] = tW3[l * 256 + i]; wbuf[OW3S + i] = sW3[l * 256 + i];
            wbuf[OW4T + i] = tW4[l * 256 + i]; wbuf[OW4S + i] = sW4[l * 256 + i];
        }
        if (tid < 64) {
            wbuf[OB5T + tid] = tb5[l * 128 + upoff + tid];
            wbuf[OB5S + tid] = sb5[l * 128 + upoff + tid];
            if (tid < 16) {
                wbuf[OB1T + tid] = tb1[l * 16 + tid]; wbuf[OB1S + tid] = sb1[l * 16 + tid];
                wbuf[OB2T + tid] = tb2[l * 16 + tid]; wbuf[OB2S + tid] = sb2[l * 16 + tid];
                wbuf[OB3T + tid] = tb3[l * 16 + tid]; wbuf[OB3S + tid] = sb3[l * 16 + tid];
                wbuf[OB4T + tid] = tb4[l * 16 + tid]; wbuf[OB4S + tid] = sb4[l * 16 + tid];
            }
        }
        __syncthreads();

        // ---- GEMM1: 64 active cols -> 16, both nets share streamed x ----
        u64 at[8], as8[8];
        {
            const u64* bt = (const u64*)(wbuf + OB1T);
            const u64* bs = (const u64*)(wbuf + OB1S);
#pragma unroll
            for (int i = 0; i < 8; i++) { at[i] = bt[i]; as8[i] = bs[i]; }
            const float* xc = xs + inoff * TRP + r;
#pragma unroll 8
            for (int k = 0; k < 64; k++) {
                float xv = xc[k * TRP];
                u64 xx = pack2(xv, xv);
                const ulonglong2* wt = (const ulonglong2*)(wbuf + OW1T + k * 16);
                const ulonglong2* ws = (const ulonglong2*)(wbuf + OW1S + k * 16);
#pragma unroll
                for (int i = 0; i < 4; i++) {
                    ulonglong2 wv = wt[i];
                    at[2 * i]     = ffma2(xx, wv.x, at[2 * i]);
                    at[2 * i + 1] = ffma2(xx, wv.y, at[2 * i + 1]);
                    ulonglong2 wv2 = ws[i];
                    as8[2 * i]     = ffma2(xx, wv2.x, as8[2 * i]);
                    as8[2 * i + 1] = ffma2(xx, wv2.y, as8[2 * i + 1]);
                }
            }
        }
        float ht[16], hs[16];
#pragma unroll
        for (int i = 0; i < 8; i++) {
            float a, b;
            unpack2(at[i], a, b);  ht[2 * i] = fmaxf(a, 0.f); ht[2 * i + 1] = fmaxf(b, 0.f);
            unpack2(as8[i], a, b); hs[2 * i] = fmaxf(a, 0.f); hs[2 * i + 1] = fmaxf(b, 0.f);
        }

        // ---- hidden 16x16 layers (register-resident) ----
        dense16_relu(ht, wbuf + OW2T, wbuf + OB2T);
        dense16_relu(hs, wbuf + OW2S, wbuf + OB2S);
        dense16_relu(ht, wbuf + OW3T, wbuf + OB3T);
        dense16_relu(hs, wbuf + OW3S, wbuf + OB3S);
        dense16_relu(ht, wbuf + OW4T, wbuf + OB4T);
        dense16_relu(hs, wbuf + OW4S, wbuf + OB4S);

        // ---- head (two 32-col chunks) + coupling update ----
        float* xu = xs + upoff * TRP + r;
#pragma unroll
        for (int jc = 0; jc < 64; jc += 32) {
            u64 ta[16], sa[16];
            const u64* bt = (const u64*)(wbuf + OB5T + jc);
            const u64* bs = (const u64*)(wbuf + OB5S + jc);
#pragma unroll
            for (int i = 0; i < 16; i++) { ta[i] = bt[i]; sa[i] = bs[i]; }
#pragma unroll
            for (int k = 0; k < 16; k++) {
                u64 xt = pack2(ht[k], ht[k]);
                u64 xv = pack2(hs[k], hs[k]);
                const ulonglong2* wt = (const ulonglong2*)(wbuf + OW5T + k * 64 + jc);
                const ulonglong2* ws = (const ulonglong2*)(wbuf + OW5S + k * 64 + jc);
#pragma unroll
                for (int i = 0; i < 8; i++) {
                    ulonglong2 wv = wt[i];
                    ta[2 * i]     = ffma2(xt, wv.x, ta[2 * i]);
                    ta[2 * i + 1] = ffma2(xt, wv.y, ta[2 * i + 1]);
                    ulonglong2 wv2 = ws[i];
                    sa[2 * i]     = ffma2(xv, wv2.x, sa[2 * i]);
                    sa[2 * i + 1] = ffma2(xv, wv2.y, sa[2 * i + 1]);
                }
            }
#pragma unroll
            for (int i = 0; i < 16; i++) {
                float t0, t1, z0, z1;
                unpack2(ta[i], t0, t1);
                unpack2(sa[i], z0, z1);
                float s0 = tanh_fast(z0), s1 = tanh_fast(z1);
                int c = jc + 2 * i;
                float x0 = xu[c * TRP];
                float x1 = xu[(c + 1) * TRP];
                xu[c * TRP]       = (x0 - t0) * __expf(-s0);
                xu[(c + 1) * TRP] = (x1 - t1) * __expf(-s1);
                ld -= s0 + s1;
            }
        }
    }

    __syncthreads();  // all rows final before transposed writeback

    // ---- write y (coalesced float4) and logdet ----
    {
        float4* yg = (float4*)(out + (size_t)row0 * 128);
        for (int idx = tid; idx < TR * 32; idx += NTHREADS) {
            int rr = idx >> 5, c4 = idx & 31;
            if (row0 + rr < rows) {
                int cb = c4 * 4;
                float4 v;
                v.x = xs[(cb + 0) * TRP + rr];
                v.y = xs[(cb + 1) * TRP + rr];
                v.z = xs[(cb + 2) * TRP + rr];
                v.w = xs[(cb + 3) * TRP + rr];
                yg[idx] = v;
            }
        }
        if (active) out[(size_t)rows * 128 + row0 + r] = ld;
    }
}

extern "C" void kernel_launch(void* const* d_in, const int* in_sizes, int n_in,
                              void* d_out, int out_size) {
    const float* x     = (const float*)d_in[0];
    const float* masks = (const float*)d_in[1];
    const float* tW1 = (const float*)d_in[2];  const float* tb1 = (const float*)d_in[3];
    const float* tW2 = (const float*)d_in[4];  const float* tb2 = (const float*)d_in[5];
    const float* tW3 = (const float*)d_in[6];  const float* tb3 = (const float*)d_in[7];
    const float* tW4 = (const float*)d_in[8];  const float* tb4 = (const float*)d_in[9];
    const float* tW5 = (const float*)d_in[10]; const float* tb5 = (const float*)d_in[11];
    const float* sW1 = (const float*)d_in[12]; const float* sb1 = (const float*)d_in[13];
    const float* sW2 = (const float*)d_in[14]; const float* sb2 = (const float*)d_in[15];
    const float* sW3 = (const float*)d_in[16]; const float* sb3 = (const float*)d_in[17];
    const float* sW4 = (const float*)d_in[18]; const float* sb4 = (const float*)d_in[19];
    const float* sW5 = (const float*)d_in[20]; const float* sb5 = (const float*)d_in[21];
    float* out = (float*)d_out;

    int rows = in_sizes[0] / 128;
    int grid = (rows + TR - 1) / TR;

    cudaFuncSetAttribute(realnvp_kernel,
                         cudaFuncAttributeMaxDynamicSharedMemorySize, SMEM_BYTES);

    realnvp_kernel<<<grid, NTHREADS, SMEM_BYTES>>>(
        x, masks, tW1, tb1, tW2, tb2, tW3, tb3, tW4, tb4, tW5, tb5,
        sW1, sb1, sW2, sb2, sW3, sb3, sW4, sb4, sW5, sb5, out, rows);
}

// round 4
// speedup vs baseline: 1.1791x; 1.1791x over previous
#include <cuda_runtime.h>

typedef unsigned long long u64;

#define NRMAX 131072
#define TRP   257
#define NT    256

// 64 MB column-pair-major scratch: g_scr[cp*NRMAX + row] = {x[row][2cp], x[row][2cp+1]}
__device__ float2 g_scr[(size_t)64 * NRMAX];

// float offsets inside one weight buffer
#define OW1T 0
#define OW1S 1024
#define OW2T 2048
#define OW2S 2304
#define OW3T 2560
#define OW3S 2816
#define OW4T 3072
#define OW4S 3328
#define OW5T 3584
#define OW5S 4608
#define OB1T 5632
#define OB1S 5648
#define OB2T 5664
#define OB2S 5680
#define OB3T 5696
#define OB3S 5712
#define OB4T 5728
#define OB4S 5744
#define OB5T 5760
#define OB5S 5824
#define WTOT 5888

__device__ __forceinline__ u64 pack2(float a, float b) {
    u64 r; asm("mov.b64 %0, {%1, %2};" : "=l"(r) : "f"(a), "f"(b)); return r;
}
__device__ __forceinline__ void unpack2(u64 v, float& a, float& b) {
    asm("mov.b64 {%0, %1}, %2;" : "=f"(a), "=f"(b) : "l"(v));
}
__device__ __forceinline__ u64 ffma2(u64 a, u64 b, u64 c) {
    u64 d; asm("fma.rn.f32x2 %0, %1, %2, %3;" : "=l"(d) : "l"(a), "l"(b), "l"(c)); return d;
}

// tanh(z) = 1 - 2/(e^{2z}+1); saturates correctly at +/-inf.
__device__ __forceinline__ float tanh_fast(float z) {
    float e = __expf(2.0f * z);
    return 1.0f - __fdividef(2.0f, e + 1.0f);
}

// ---- stage one layer's weights into a buffer (cooperative, 256 threads) ----
__device__ __forceinline__ void stage_weights(
    float* wb, int l, int inoff, int upoff, int tid,
    const float* tW1, const float* tb1, const float* tW2, const float* tb2,
    const float* tW3, const float* tb3, const float* tW4, const float* tb4,
    const float* tW5, const float* tb5,
    const float* sW1, const float* sb1, const float* sW2, const float* sb2,
    const float* sW3, const float* sb3, const float* sW4, const float* sb4,
    const float* sW5, const float* sb5) {
    for (int i = tid; i < 1024; i += NT) {
        wb[OW1T + i] = tW1[l * 2048 + inoff * 16 + i];
        wb[OW1S + i] = sW1[l * 2048 + inoff * 16 + i];
        int k = i >> 6, j = i & 63;
        wb[OW5T + i] = tW5[l * 2048 + k * 128 + upoff + j];
        wb[OW5S + i] = sW5[l * 2048 + k * 128 + upoff + j];
    }
    {
        int i = tid;  // 256 threads cover each 16x16 in one shot
        wb[OW2T + i] = tW2[l * 256 + i]; wb[OW2S + i] = sW2[l * 256 + i];
        wb[OW3T + i] = tW3[l * 256 + i]; wb[OW3S + i] = sW3[l * 256 + i];
        wb[OW4T + i] = tW4[l * 256 + i]; wb[OW4S + i] = sW4[l * 256 + i];
    }
    if (tid < 64) {
        wb[OB5T + tid] = tb5[l * 128 + upoff + tid];
        wb[OB5S + tid] = sb5[l * 128 + upoff + tid];
        if (tid < 16) {
            wb[OB1T + tid] = tb1[l * 16 + tid]; wb[OB1S + tid] = sb1[l * 16 + tid];
            wb[OB2T + tid] = tb2[l * 16 + tid]; wb[OB2S + tid] = sb2[l * 16 + tid];
            wb[OB3T + tid] = tb3[l * 16 + tid]; wb[OB3S + tid] = sb3[l * 16 + tid];
            wb[OB4T + tid] = tb4[l * 16 + tid]; wb[OB4S + tid] = sb4[l * 16 + tid];
        }
    }
}

// ---- dense 16->16 + relu for TWO rows sharing one weight-load stream ----
__device__ __forceinline__ void dense2(float* p, float* q, const float* w, const float* b) {
    u64 a0[8], a1[8];
    const u64* bp = (const u64*)b;
#pragma unroll
    for (int i = 0; i < 8; i++) { a0[i] = bp[i]; a1[i] = bp[i]; }
#pragma unroll
    for (int k = 0; k < 16; k++) {
        u64 x0 = pack2(p[k], p[k]);
        u64 x1 = pack2(q[k], q[k]);
        const ulonglong2* wp = (const ulonglong2*)(w + k * 16);
#pragma unroll
        for (int i = 0; i < 4; i++) {
            ulonglong2 wv = wp[i];
            a0[2 * i]     = ffma2(x0, wv.x, a0[2 * i]);
            a0[2 * i + 1] = ffma2(x0, wv.y, a0[2 * i + 1]);
            a1[2 * i]     = ffma2(x1, wv.x, a1[2 * i]);
            a1[2 * i + 1] = ffma2(x1, wv.y, a1[2 * i + 1]);
        }
    }
#pragma unroll
    for (int i = 0; i < 8; i++) {
        float a, b2;
        unpack2(a0[i], a, b2); p[2 * i] = fmaxf(a, 0.f); p[2 * i + 1] = fmaxf(b2, 0.f);
        unpack2(a1[i], a, b2); q[2 * i] = fmaxf(a, 0.f); q[2 * i + 1] = fmaxf(b2, 0.f);
    }
}

// ---- pre-transpose: x row-major -> col-pair-major scratch ----
__global__ void __launch_bounds__(NT) pre_t(const float* __restrict__ x, int rows) {
    extern __shared__ float xs[];
    const int tid = threadIdx.x, row0 = blockIdx.x * 256;
    const float4* xg = (const float4*)(x + (size_t)row0 * 128);
    for (int idx = tid; idx < 256 * 32; idx += NT) {
        int rr = idx >> 5, c4 = idx & 31;
        if (row0 + rr < rows) {
            float4 v = xg[idx];
            int cb = c4 * 4;
            xs[(cb + 0) * TRP + rr] = v.x;
            xs[(cb + 1) * TRP + rr] = v.y;
            xs[(cb + 2) * TRP + rr] = v.z;
            xs[(cb + 3) * TRP + rr] = v.w;
        }
    }
    __syncthreads();
    const int r = tid;
    if (row0 + r < rows) {
#pragma unroll 4
        for (int cp = 0; cp < 64; cp++) {
            g_scr[(size_t)cp * NRMAX + row0 + r] =
                make_float2(xs[(2 * cp) * TRP + r], xs[(2 * cp + 1) * TRP + r]);
        }
    }
}

// ---- post-transpose: scratch -> y row-major ----
__global__ void __launch_bounds__(NT) post_t(float* __restrict__ out, int rows) {
    extern __shared__ float xs[];
    const int tid = threadIdx.x, row0 = blockIdx.x * 256, r = tid;
    if (row0 + r < rows) {
#pragma unroll 4
        for (int cp = 0; cp < 64; cp++) {
            float2 v = g_scr[(size_t)cp * NRMAX + row0 + r];
            xs[(2 * cp) * TRP + r]     = v.x;
            xs[(2 * cp + 1) * TRP + r] = v.y;
        }
    }
    __syncthreads();
    float4* yg = (float4*)(out + (size_t)row0 * 128);
    for (int idx = tid; idx < 256 * 32; idx += NT) {
        int rr = idx >> 5, c4 = idx & 31;
        if (row0 + rr < rows) {
            int cb = c4 * 4;
            float4 v;
            v.x = xs[(cb + 0) * TRP + rr];
            v.y = xs[(cb + 1) * TRP + rr];
            v.z = xs[(cb + 2) * TRP + rr];
            v.w = xs[(cb + 3) * TRP + rr];
            yg[idx] = v;
        }
    }
}

// ---- main: 6 coupling layers, 2 rows/thread, x in L2 scratch ----
__global__ void __launch_bounds__(NT, 1)
nvp_main(const float* __restrict__ masks,
         const float* __restrict__ tW1, const float* __restrict__ tb1,
         const float* __restrict__ tW2, const float* __restrict__ tb2,
         const float* __restrict__ tW3, const float* __restrict__ tb3,
         const float* __restrict__ tW4, const float* __restrict__ tb4,
         const float* __restrict__ tW5, const float* __restrict__ tb5,
         const float* __restrict__ sW1, const float* __restrict__ sb1,
         const float* __restrict__ sW2, const float* __restrict__ sb2,
         const float* __restrict__ sW3, const float* __restrict__ sb3,
         const float* __restrict__ sW4, const float* __restrict__ sb4,
         const float* __restrict__ sW5, const float* __restrict__ sb5,
         float* __restrict__ out, int rows) {
    __shared__ float wb[2][WTOT];

    const int tid = threadIdx.x;
    const int base = blockIdx.x * (NT * 2);
    const int g0 = base + 2 * tid;      // even
    const int g1 = g0 + 1;
    const bool act = (g1 < rows);       // rows is even

    int inof[6];
#pragma unroll
    for (int l = 0; l < 6; l++) inof[l] = (masks[l * 128] > 0.5f) ? 0 : 64;

    stage_weights(wb[0], 5, inof[5], 64 - inof[5], tid,
                  tW1, tb1, tW2, tb2, tW3, tb3, tW4, tb4, tW5, tb5,
                  sW1, sb1, sW2, sb2, sW3, sb3, sW4, sb4, sW5, sb5);
    __syncthreads();

    float ld0 = 0.f, ld1 = 0.f;

#pragma unroll 1
    for (int li = 0; li < 6; ++li) {
        const int l = 5 - li;
        const float* w = wb[li & 1];
        const int inoff = inof[l];
        const int upoff = 64 - inoff;

        if (li < 5) {
            stage_weights(wb[(li + 1) & 1], l - 1, inof[l - 1], 64 - inof[l - 1], tid,
                          tW1, tb1, tW2, tb2, tW3, tb3, tW4, tb4, tW5, tb5,
                          sW1, sb1, sW2, sb2, sW3, sb3, sW4, sb4, sW5, sb5);
        }

        if (act) {
            // ---- GEMM1: 64 active cols -> 16, both nets, both rows ----
            u64 a0t[8], a0s[8], a1t[8], a1s[8];
            {
                const u64* bt = (const u64*)(w + OB1T);
                const u64* bs = (const u64*)(w + OB1S);
#pragma unroll
                for (int i = 0; i < 8; i++) {
                    a0t[i] = bt[i]; a1t[i] = bt[i];
                    a0s[i] = bs[i]; a1s[i] = bs[i];
                }
                const float2* xin = g_scr + (size_t)(inoff >> 1) * NRMAX;
#pragma unroll 4
                for (int cp = 0; cp < 32; cp++) {
                    float4 v = *(const float4*)(xin + (size_t)cp * NRMAX + g0);
#pragma unroll
                    for (int kk = 0; kk < 2; kk++) {
                        const int k = 2 * cp + kk;
                        float x0 = kk ? v.y : v.x;
                        float x1 = kk ? v.w : v.z;
                        u64 xx0 = pack2(x0, x0);
                        u64 xx1 = pack2(x1, x1);
                        const ulonglong2* wt = (const ulonglong2*)(w + OW1T + k * 16);
                        const ulonglong2* ws = (const ulonglong2*)(w + OW1S + k * 16);
#pragma unroll
                        for (int i = 0; i < 4; i++) {
                            ulonglong2 wv = wt[i];
                            a0t[2 * i]     = ffma2(xx0, wv.x, a0t[2 * i]);
                            a0t[2 * i + 1] = ffma2(xx0, wv.y, a0t[2 * i + 1]);
                            a1t[2 * i]     = ffma2(xx1, wv.x, a1t[2 * i]);
                            a1t[2 * i + 1] = ffma2(xx1, wv.y, a1t[2 * i + 1]);
                            ulonglong2 w2 = ws[i];
                            a0s[2 * i]     = ffma2(xx0, w2.x, a0s[2 * i]);
                            a0s[2 * i + 1] = ffma2(xx0, w2.y, a0s[2 * i + 1]);
                            a1s[2 * i]     = ffma2(xx1, w2.x, a1s[2 * i]);
                            a1s[2 * i + 1] = ffma2(xx1, w2.y, a1s[2 * i + 1]);
                        }
                    }
                }
            }
            float h0t[16], h0s[16], h1t[16], h1s[16];
#pragma unroll
            for (int i = 0; i < 8; i++) {
                float a, b;
                unpack2(a0t[i], a, b); h0t[2 * i] = fmaxf(a, 0.f); h0t[2 * i + 1] = fmaxf(b, 0.f);
                unpack2(a0s[i], a, b); h0s[2 * i] = fmaxf(a, 0.f); h0s[2 * i + 1] = fmaxf(b, 0.f);
                unpack2(a1t[i], a, b); h1t[2 * i] = fmaxf(a, 0.f); h1t[2 * i + 1] = fmaxf(b, 0.f);
                unpack2(a1s[i], a, b); h1s[2 * i] = fmaxf(a, 0.f); h1s[2 * i + 1] = fmaxf(b, 0.f);
            }

            // ---- hidden 16x16 layers ----
            dense2(h0t, h1t, w + OW2T, w + OB2T);
            dense2(h0s, h1s, w + OW2S, w + OB2S);
            dense2(h0t, h1t, w + OW3T, w + OB3T);
            dense2(h0s, h1s, w + OW3S, w + OB3S);
            dense2(h0t, h1t, w + OW4T, w + OB4T);
            dense2(h0s, h1s, w + OW4S, w + OB4S);

            // ---- head (four 16-col chunks) + coupling update ----
            float2* xup = g_scr + (size_t)(upoff >> 1) * NRMAX;
#pragma unroll 1
            for (int jc = 0; jc < 64; jc += 16) {
                u64 t0[8], s0[8], t1[8], s1[8];
                const u64* bt = (const u64*)(w + OB5T + jc);
                const u64* bs = (const u64*)(w + OB5S + jc);
#pragma unroll
                for (int i = 0; i < 8; i++) {
                    t0[i] = bt[i]; t1[i] = bt[i];
                    s0[i] = bs[i]; s1[i] = bs[i];
                }
#pragma unroll
                for (int k = 0; k < 16; k++) {
                    u64 xt0 = pack2(h0t[k], h0t[k]);
                    u64 xt1 = pack2(h1t[k], h1t[k]);
                    u64 xs0 = pack2(h0s[k], h0s[k]);
                    u64 xs1 = pack2(h1s[k], h1s[k]);
                    const ulonglong2* wt = (const ulonglong2*)(w + OW5T + k * 64 + jc);
                    const ulonglong2* ws = (const ulonglong2*)(w + OW5S + k * 64 + jc);
#pragma unroll
                    for (int i = 0; i < 4; i++) {
                        ulonglong2 wv = wt[i];
                        t0[2 * i]     = ffma2(xt0, wv.x, t0[2 * i]);
                        t0[2 * i + 1] = ffma2(xt0, wv.y, t0[2 * i + 1]);
                        t1[2 * i]     = ffma2(xt1, wv.x, t1[2 * i]);
                        t1[2 * i + 1] = ffma2(xt1, wv.y, t1[2 * i + 1]);
                        ulonglong2 w2 = ws[i];
                        s0[2 * i]     = ffma2(xs0, w2.x, s0[2 * i]);
                        s0[2 * i + 1] = ffma2(xs0, w2.y, s0[2 * i + 1]);
                        s1[2 * i]     = ffma2(xs1, w2.x, s1[2 * i]);
                        s1[2 * i + 1] = ffma2(xs1, w2.y, s1[2 * i + 1]);
                    }
                }
                // update cols [upoff+jc, upoff+jc+16)
#pragma unroll
                for (int i = 0; i < 8; i++) {
                    float4* xp = (float4*)(xup + (size_t)((jc >> 1) + i) * NRMAX + g0);
                    float4 xv = *xp;
                    float ta, tb, za, zb, sa, sb;
                    unpack2(t0[i], ta, tb);
                    unpack2(s0[i], za, zb);
                    sa = tanh_fast(za); sb = tanh_fast(zb);
                    xv.x = (xv.x - ta) * __expf(-sa);
                    xv.y = (xv.y - tb) * __expf(-sb);
                    ld0 -= sa + sb;
                    unpack2(t1[i], ta, tb);
                    unpack2(s1[i], za, zb);
                    sa = tanh_fast(za); sb = tanh_fast(zb);
                    xv.z = (xv.z - ta) * __expf(-sa);
                    xv.w = (xv.w - tb) * __expf(-sb);
                    ld1 -= sa + sb;
                    *xp = xv;
                }
            }
        }
        __syncthreads();
    }

    if (act) {
        out[(size_t)rows * 128 + g0] = ld0;
        out[(size_t)rows * 128 + g1] = ld1;
    }
}

extern "C" void kernel_launch(void* const* d_in, const int* in_sizes, int n_in,
                              void* d_out, int out_size) {
    const float* x     = (const float*)d_in[0];
    const float* masks = (const float*)d_in[1];
    const float* tW1 = (const float*)d_in[2];  const float* tb1 = (const float*)d_in[3];
    const float* tW2 = (const float*)d_in[4];  const float* tb2 = (const float*)d_in[5];
    const float* tW3 = (const float*)d_in[6];  const float* tb3 = (const float*)d_in[7];
    const float* tW4 = (const float*)d_in[8];  const float* tb4 = (const float*)d_in[9];
    const float* tW5 = (const float*)d_in[10]; const float* tb5 = (const float*)d_in[11];
    const float* sW1 = (const float*)d_in[12]; const float* sb1 = (const float*)d_in[13];
    const float* sW2 = (const float*)d_in[14]; const float* sb2 = (const float*)d_in[15];
    const float* sW3 = (const float*)d_in[16]; const float* sb3 = (const float*)d_in[17];
    const float* sW4 = (const float*)d_in[18]; const float* sb4 = (const float*)d_in[19];
    const float* sW5 = (const float*)d_in[20]; const float* sb5 = (const float*)d_in[21];
    float* out = (float*)d_out;

    const int rows = in_sizes[0] / 128;
    const int TSMEM = 128 * TRP * 4;

    cudaFuncSetAttribute(pre_t,  cudaFuncAttributeMaxDynamicSharedMemorySize, TSMEM);
    cudaFuncSetAttribute(post_t, cudaFuncAttributeMaxDynamicSharedMemorySize, TSMEM);

    int tgrid = (rows + 255) / 256;
    int mgrid = (rows + 511) / 512;

    pre_t<<<tgrid, NT, TSMEM>>>(x, rows);
    nvp_main<<<mgrid, NT>>>(masks,
                            tW1, tb1, tW2, tb2, tW3, tb3, tW4, tb4, tW5, tb5,
                            sW1, sb1, sW2, sb2, sW3, sb3, sW4, sb4, sW5, sb5,
                            out, rows);
    post_t<<<tgrid, NT, TSMEM>>>(out, rows);
}